// round 16
// baseline (speedup 1.0000x reference)
#include <cuda_runtime.h>
#include <cuda_bf16.h>

#define EPSn 1e-5f

// ---------------- device scratch (no allocs allowed) ----------------
__device__ float g_tf[100000 * 128];
// tf32 fragment-ordered weights: idx ((nb*KSP+ksp)*32+4g+t)*4 + kodd*2 + rho
__device__ __align__(256) unsigned g_W1t[128 * 256];   // KSP=16 (K=256), 128KB
__device__ __align__(256) unsigned g_W2t[128 * 128];   // KSP=8
__device__ __align__(256) unsigned g_Wint[128 * 128];
__device__ __align__(256) unsigned g_Wm1t[128 * 128];
__device__ __align__(256) unsigned g_Wm2t[128 * 128];

__device__ __forceinline__ unsigned f2tf(float x) {
    unsigned u;
    asm("cvt.rna.tf32.f32 %0, %1;" : "=r"(u) : "f"(x));
    return u;
}

__device__ __forceinline__ void mma_tf32(float* c, unsigned a0, unsigned a1,
                                         unsigned a2, unsigned a3,
                                         unsigned b0, unsigned b1) {
    asm volatile(
        "mma.sync.aligned.m16n8k8.row.col.f32.tf32.tf32.f32 "
        "{%0,%1,%2,%3},{%4,%5,%6,%7},{%8,%9},{%0,%1,%2,%3};"
        : "+f"(c[0]), "+f"(c[1]), "+f"(c[2]), "+f"(c[3])
        : "r"(a0), "r"(a1), "r"(a2), "r"(a3), "r"(b0), "r"(b1));
}

// ---------------------------------------------------------------------------
// K0: weight prep — tf32 fragment order.
// ---------------------------------------------------------------------------
extern "C" __global__ void k0_prep(const float* __restrict__ Win,
                                   const float* __restrict__ W1,
                                   const float* __restrict__ W2,
                                   const float* __restrict__ Wm1,
                                   const float* __restrict__ Wm2) {
    int i = blockIdx.x * blockDim.x + threadIdx.x;
    if (i < 128 * 256) {          // W1: K=256, KSP=16
        int n = i >> 8, k = i & 255;
        int nb = n >> 3, g = n & 7;
        int ks = k >> 3, kc = k & 7, t = kc >> 1, rho = kc & 1;
        int ksp = ks >> 1, kodd = ks & 1;
        int b = (((nb * 16 + ksp) * 32 + 4 * g + t) << 2) + kodd * 2 + rho;
        g_W1t[b] = f2tf(W1[k * 128 + n]);
    }
    if (i < 128 * 128) {          // K=128, KSP=8
        int n = i >> 7, k = i & 127;
        int nb = n >> 3, g = n & 7;
        int ks = k >> 3, kc = k & 7, t = kc >> 1, rho = kc & 1;
        int ksp = ks >> 1, kodd = ks & 1;
        int b = (((nb * 8 + ksp) * 32 + 4 * g + t) << 2) + kodd * 2 + rho;
        g_W2t[b]  = f2tf(W2[k * 128 + n]);
        g_Wint[b] = f2tf(Win[k * 128 + n]);
        g_Wm1t[b] = f2tf(Wm1[k * 128 + n]);
        g_Wm2t[b] = f2tf(Wm2[k * 128 + n]);
    }
}

// ---------------------------------------------------------------------------
// kzero: g_tf = 0
// ---------------------------------------------------------------------------
extern "C" __global__ void kzero(int n4) {
    float4 z = make_float4(0.f, 0.f, 0.f, 0.f);
    for (int i = blockIdx.x * blockDim.x + threadIdx.x; i < n4;
         i += gridDim.x * blockDim.x)
        ((float4*)g_tf)[i] = z;
}

// ---------------------------------------------------------------------------
// kfused: barrier-free edge pipeline + W_in projection, tf32.
// Edge blocks reordered: gathers issued first, relpose+mma-half1 run in the
// gather shadow, then half0 converts + mmas.
// ---------------------------------------------------------------------------
extern "C" __global__ void __launch_bounds__(256, 1)
kfused(const float* __restrict__ cfeat, const float* __restrict__ cpose,
       const float* __restrict__ tpose, const int* __restrict__ hiA,
       const int* __restrict__ wiA, const float* __restrict__ Wrp,
       const float* __restrict__ brp, const float* __restrict__ gcv,
       const float* __restrict__ bcv, const float* __restrict__ tfeat,
       int E, int Nt) {
    extern __shared__ unsigned smu[];
    unsigned* W1S = smu;              // 32768 words (128KB)
    unsigned* W2S = W1S + 32768;      // 16384 words (64KB)
    float4* wrp4_s = (float4*)(W2S + 16384);  // 128 float4
    float* brp_s = (float*)(wrp4_s + 128);    // 128
    float* gc_s  = brp_s + 128;               // 128
    float* bc_s  = gc_s + 128;                // 128

    const int tid = threadIdx.x;
    for (int i = tid; i < 32768; i += 256) W1S[i] = g_W1t[i];
    for (int i = tid; i < 16384; i += 256) W2S[i] = g_W2t[i];
    if (tid < 128) {
        wrp4_s[tid] = make_float4(Wrp[tid], Wrp[128 + tid], Wrp[256 + tid], Wrp[384 + tid]);
        brp_s[tid] = brp[tid];
        gc_s[tid] = gcv[tid];
        bc_s[tid] = bcv[tid];
    }
    __syncthreads();   // the only block barrier

    const int warp = tid >> 5, lane = tid & 31;
    const int g = lane >> 2, t = lane & 3;
    const int gw = blockIdx.x * 8 + warp;
    const int nw = gridDim.x * 8;
    const int nbe = (E + 15) >> 4;
    const int nbr = (Nt + 15) >> 4;

    for (int b16 = gw; b16 < nbe + nbr; b16 += nw) {
        if (b16 < nbe) {
            const int eb = b16 << 4;
            const int e0 = eb + g, e8 = eb + g + 8;
            const bool v0 = e0 < E, v8 = e8 < E;
            const int h0i = hiA[min(e0, E - 1)], h8i = hiA[min(e8, E - 1)];
            const int w0i = wiA[min(e0, E - 1)], w8i = wiA[min(e8, E - 1)];

            float acc[16][4];
#pragma unroll
            for (int nb = 0; nb < 16; nb++) {
                acc[nb][0] = 0.f; acc[nb][1] = 0.f; acc[nb][2] = 0.f; acc[nb][3] = 0.f;
            }

            // ---- phase 1: issue all cfeat gathers (non-blocking) ----
            float2 f0r[16], f8r[16];
            {
                const float2* c0p = (const float2*)(cfeat + (size_t)h0i * 128);
                const float2* c8p = (const float2*)(cfeat + (size_t)h8i * 128);
#pragma unroll
                for (int j = 0; j < 16; j++) {
                    f0r[j] = c0p[4 * j + t];
                    f8r[j] = c8p[4 * j + t];
                }
            }

            unsigned A[16][4];

            // ---- phase 2: relpose MLP -> half1 A frags (ALU, independent) ----
            {
                float4 cpg = *(const float4*)(cpose + 4 * (size_t)h0i);
                float4 tpg = *(const float4*)(tpose + 4 * (size_t)w0i);
                float4 cp8 = *(const float4*)(cpose + 4 * (size_t)h8i);
                float4 tp8 = *(const float4*)(tpose + 4 * (size_t)w8i);
                float dg0 = cpg.x - tpg.x, dg1 = cpg.y - tpg.y;
                float dg2 = cpg.z - tpg.z, dg3 = cpg.w - tpg.w;
                float d80 = cp8.x - tp8.x, d81 = cp8.y - tp8.y;
                float d82 = cp8.z - tp8.z, d83 = cp8.w - tp8.w;
#pragma unroll
                for (int j = 0; j < 16; j++) {
                    int c0 = 8 * j + 2 * t;
                    float4 wA = wrp4_s[c0], wB = wrp4_s[c0 + 1];
                    float bA = brp_s[c0], bB = brp_s[c0 + 1];
                    float rg0 = fmaxf(bA + dg0 * wA.x + dg1 * wA.y + dg2 * wA.z + dg3 * wA.w, 0.f);
                    float rg1 = fmaxf(bB + dg0 * wB.x + dg1 * wB.y + dg2 * wB.z + dg3 * wB.w, 0.f);
                    float r80 = fmaxf(bA + d80 * wA.x + d81 * wA.y + d82 * wA.z + d83 * wA.w, 0.f);
                    float r81 = fmaxf(bB + d80 * wB.x + d81 * wB.y + d82 * wB.z + d83 * wB.w, 0.f);
                    A[j][0] = f2tf(rg0); A[j][1] = f2tf(r80);
                    A[j][2] = f2tf(rg1); A[j][3] = f2tf(r81);
                }
            }

            // ---- phase 3: mma k-half1 (gathers still landing) ----
#pragma unroll
            for (int ksp = 0; ksp < 8; ksp++) {
#pragma unroll
                for (int nb = 0; nb < 16; nb++) {
                    unsigned off = (unsigned)(((nb * 16 + 8 + ksp) * 32 + lane) << 2);
                    uint4 B = *(const uint4*)(W1S + off);
                    mma_tf32(acc[nb], A[2 * ksp][0], A[2 * ksp][1],
                             A[2 * ksp][2], A[2 * ksp][3], B.x, B.y);
                    mma_tf32(acc[nb], A[2 * ksp + 1][0], A[2 * ksp + 1][1],
                             A[2 * ksp + 1][2], A[2 * ksp + 1][3], B.z, B.w);
                }
            }

            // ---- phase 4: convert gathered cfeat -> half0 A frags ----
#pragma unroll
            for (int j = 0; j < 16; j++) {
                A[j][0] = f2tf(f0r[j].x); A[j][1] = f2tf(f8r[j].x);
                A[j][2] = f2tf(f0r[j].y); A[j][3] = f2tf(f8r[j].y);
            }

            // ---- phase 5: mma k-half0 ----
#pragma unroll
            for (int ksp = 0; ksp < 8; ksp++) {
#pragma unroll
                for (int nb = 0; nb < 16; nb++) {
                    unsigned off = (unsigned)(((nb * 16 + ksp) * 32 + lane) << 2);
                    uint4 B = *(const uint4*)(W1S + off);
                    mma_tf32(acc[nb], A[2 * ksp][0], A[2 * ksp][1],
                             A[2 * ksp][2], A[2 * ksp][3], B.x, B.y);
                    mma_tf32(acc[nb], A[2 * ksp + 1][0], A[2 * ksp + 1][1],
                             A[2 * ksp + 1][2], A[2 * ksp + 1][3], B.z, B.w);
                }
            }

            // ---- GN + relu -> Hf (tf32 A frags in registers) ----
            unsigned Hf[16][4];
            {
                float s1a = 0.f, s2a = 0.f, s1b = 0.f, s2b = 0.f;
#pragma unroll
                for (int nb = 0; nb < 16; nb++) {
                    s1a += acc[nb][0] + acc[nb][1];
                    s2a += acc[nb][0] * acc[nb][0] + acc[nb][1] * acc[nb][1];
                    s1b += acc[nb][2] + acc[nb][3];
                    s2b += acc[nb][2] * acc[nb][2] + acc[nb][3] * acc[nb][3];
                }
#pragma unroll
                for (int off = 1; off <= 2; off <<= 1) {
                    s1a += __shfl_xor_sync(0xffffffffu, s1a, off);
                    s2a += __shfl_xor_sync(0xffffffffu, s2a, off);
                    s1b += __shfl_xor_sync(0xffffffffu, s1b, off);
                    s2b += __shfl_xor_sync(0xffffffffu, s2b, off);
                }
                float mua = s1a * 0.0078125f;
                float rsa = rsqrtf(s2a * 0.0078125f - mua * mua + EPSn);
                float mub = s1b * 0.0078125f;
                float rsb = rsqrtf(s2b * 0.0078125f - mub * mub + EPSn);
#pragma unroll
                for (int nb = 0; nb < 16; nb++) {
                    int c0 = 8 * nb + 2 * t;
                    float ga = gc_s[c0], gb = gc_s[c0 + 1];
                    float ba = bc_s[c0], bb = bc_s[c0 + 1];
                    float h0 = fmaxf((acc[nb][0] - mua) * rsa * ga + ba, 0.f);
                    float h1 = fmaxf((acc[nb][1] - mua) * rsa * gb + bb, 0.f);
                    float h2 = fmaxf((acc[nb][2] - mub) * rsb * ga + ba, 0.f);
                    float h3 = fmaxf((acc[nb][3] - mub) * rsb * gb + bb, 0.f);
                    Hf[nb][0] = f2tf(h0); Hf[nb][1] = f2tf(h2);
                    Hf[nb][2] = f2tf(h1); Hf[nb][3] = f2tf(h3);
                }
            }

            // ---- GEMM2 (ksp outer, nb inner into acc) + scatter ----
#pragma unroll
            for (int nb = 0; nb < 16; nb++) {
                acc[nb][0] = 0.f; acc[nb][1] = 0.f; acc[nb][2] = 0.f; acc[nb][3] = 0.f;
            }
#pragma unroll
            for (int ksp = 0; ksp < 8; ksp++) {
#pragma unroll
                for (int nb = 0; nb < 16; nb++) {
                    unsigned off = (unsigned)(((nb * 8 + ksp) * 32 + lane) << 2);
                    uint4 B = *(const uint4*)(W2S + off);
                    mma_tf32(acc[nb], Hf[2 * ksp][0], Hf[2 * ksp][1],
                             Hf[2 * ksp][2], Hf[2 * ksp][3], B.x, B.y);
                    mma_tf32(acc[nb], Hf[2 * ksp + 1][0], Hf[2 * ksp + 1][1],
                             Hf[2 * ksp + 1][2], Hf[2 * ksp + 1][3], B.z, B.w);
                }
            }
            {
                float* dst0 = g_tf + (size_t)w0i * 128 + 2 * t;
                float* dst8 = g_tf + (size_t)w8i * 128 + 2 * t;
#pragma unroll
                for (int nb = 0; nb < 16; nb++) {
                    if (v0)
                        asm volatile("red.global.add.v2.f32 [%0], {%1,%2};"
                                     :: "l"(dst0 + 8 * nb), "f"(acc[nb][0]), "f"(acc[nb][1]) : "memory");
                    if (v8)
                        asm volatile("red.global.add.v2.f32 [%0], {%1,%2};"
                                     :: "l"(dst8 + 8 * nb), "f"(acc[nb][2]), "f"(acc[nb][3]) : "memory");
                }
            }
        } else {
            // ---- row block: W_in projection (weights from L2-hot global) ----
            const int rb = (b16 - nbe) << 4;
            const int r0r = rb + g, r8r = rb + g + 8;
            const bool v0 = r0r < Nt, v8 = r8r < Nt;
            const float2* c0p = (const float2*)(tfeat + (size_t)min(r0r, Nt - 1) * 128);
            const float2* c8p = (const float2*)(tfeat + (size_t)min(r8r, Nt - 1) * 128);

            unsigned A[16][4];
#pragma unroll
            for (int j = 0; j < 16; j++) {
                float2 f0 = c0p[4 * j + t];
                float2 f8 = c8p[4 * j + t];
                A[j][0] = f2tf(f0.x); A[j][1] = f2tf(f8.x);
                A[j][2] = f2tf(f0.y); A[j][3] = f2tf(f8.y);
            }

            float acc[16][4];
#pragma unroll
            for (int nb = 0; nb < 16; nb++) {
                acc[nb][0] = 0.f; acc[nb][1] = 0.f; acc[nb][2] = 0.f; acc[nb][3] = 0.f;
            }
#pragma unroll
            for (int ksp = 0; ksp < 8; ksp++) {
#pragma unroll
                for (int nb = 0; nb < 16; nb++) {
                    unsigned off = (unsigned)(((nb * 8 + ksp) * 32 + lane) << 2);
                    uint4 B = *(const uint4*)(g_Wint + off);
                    mma_tf32(acc[nb], A[2 * ksp][0], A[2 * ksp][1],
                             A[2 * ksp][2], A[2 * ksp][3], B.x, B.y);
                    mma_tf32(acc[nb], A[2 * ksp + 1][0], A[2 * ksp + 1][1],
                             A[2 * ksp + 1][2], A[2 * ksp + 1][3], B.z, B.w);
                }
            }
            {
                float* dst0 = g_tf + (size_t)r0r * 128 + 2 * t;
                float* dst8 = g_tf + (size_t)r8r * 128 + 2 * t;
#pragma unroll
                for (int nb = 0; nb < 16; nb++) {
                    if (v0)
                        asm volatile("red.global.add.v2.f32 [%0], {%1,%2};"
                                     :: "l"(dst0 + 8 * nb), "f"(acc[nb][0]), "f"(acc[nb][1]) : "memory");
                    if (v8)
                        asm volatile("red.global.add.v2.f32 [%0], {%1,%2};"
                                     :: "l"(dst8 + 8 * nb), "f"(acc[nb][2]), "f"(acc[nb][3]) : "memory");
                }
            }
        }
    }
}

// ---------------------------------------------------------------------------
// k3fused: barrier-free node tail, tf32 (unchanged, validated).
// ---------------------------------------------------------------------------
extern "C" __global__ void __launch_bounds__(256, 1)
k3fused(const float* __restrict__ tfeat,
        const float* __restrict__ gn,  const float* __restrict__ ben,
        const float* __restrict__ g1,  const float* __restrict__ b1,
        const float* __restrict__ g2,  const float* __restrict__ b2,
        float* __restrict__ out, int Nt) {
    extern __shared__ unsigned smu[];
    unsigned* W1S = smu;              // 16384
    unsigned* W2S = W1S + 16384;      // 16384
    float* ps = (float*)(W2S + 16384); // 768

    const int tid = threadIdx.x;
    for (int i = tid; i < 16384; i += 256) { W1S[i] = g_Wm1t[i]; W2S[i] = g_Wm2t[i]; }
    if (tid < 128) {
        ps[tid]       = gn[tid];  ps[128 + tid] = ben[tid];
        ps[256 + tid] = g1[tid];  ps[384 + tid] = b1[tid];
        ps[512 + tid] = g2[tid];  ps[640 + tid] = b2[tid];
    }
    __syncthreads();   // the only block barrier

    const int warp = tid >> 5, lane = tid & 31;
    const int g = lane >> 2, t = lane & 3;
    const int gw = blockIdx.x * 8 + warp;
    const int nw = gridDim.x * 8;
    const int nbr = (Nt + 15) >> 4;

    for (int b16 = gw; b16 < nbr; b16 += nw) {
        const int rb = b16 << 4;
        const int r0r = rb + g, r8r = rb + g + 8;
        const bool v0 = r0r < Nt, v8 = r8r < Nt;
        const int r0c = min(r0r, Nt - 1), r8c = min(r8r, Nt - 1);

        // ---- load g_tf rows + input GN -> tf32 A frags ----
        unsigned A[16][4];
        {
            float2 e0[16], e8[16];
            float s10 = 0.f, s20 = 0.f, s18 = 0.f, s28 = 0.f;
            const float2* c0p = (const float2*)(g_tf + (size_t)r0c * 128);
            const float2* c8p = (const float2*)(g_tf + (size_t)r8c * 128);
#pragma unroll
            for (int j = 0; j < 16; j++) {
                e0[j] = c0p[4 * j + t];
                e8[j] = c8p[4 * j + t];
                s10 += e0[j].x + e0[j].y;
                s20 += e0[j].x * e0[j].x + e0[j].y * e0[j].y;
                s18 += e8[j].x + e8[j].y;
                s28 += e8[j].x * e8[j].x + e8[j].y * e8[j].y;
            }
#pragma unroll
            for (int off = 1; off <= 2; off <<= 1) {
                s10 += __shfl_xor_sync(0xffffffffu, s10, off);
                s20 += __shfl_xor_sync(0xffffffffu, s20, off);
                s18 += __shfl_xor_sync(0xffffffffu, s18, off);
                s28 += __shfl_xor_sync(0xffffffffu, s28, off);
            }
            float mu0 = s10 * 0.0078125f;
            float rs0 = rsqrtf(s20 * 0.0078125f - mu0 * mu0 + EPSn);
            float mu8 = s18 * 0.0078125f;
            float rs8 = rsqrtf(s28 * 0.0078125f - mu8 * mu8 + EPSn);
#pragma unroll
            for (int j = 0; j < 16; j++) {
                int c = 8 * j + 2 * t;
                float gna = ps[c], gnb = ps[c + 1];
                float bea = ps[128 + c], beb = ps[129 + c];
                float a0 = fmaxf((e0[j].x - mu0) * rs0 * gna + bea, 0.f);
                float a1 = fmaxf((e0[j].y - mu0) * rs0 * gnb + beb, 0.f);
                float c0_ = fmaxf((e8[j].x - mu8) * rs8 * gna + bea, 0.f);
                float c1_ = fmaxf((e8[j].y - mu8) * rs8 * gnb + beb, 0.f);
                A[j][0] = f2tf(a0); A[j][1] = f2tf(c0_);
                A[j][2] = f2tf(a1); A[j][3] = f2tf(c1_);
            }
        }

        // ---- GEMM1: a @ Wm1 (ksp outer, nb inner) ----
        float acc[16][4];
#pragma unroll
        for (int nb = 0; nb < 16; nb++) {
            acc[nb][0] = 0.f; acc[nb][1] = 0.f; acc[nb][2] = 0.f; acc[nb][3] = 0.f;
        }
#pragma unroll
        for (int ksp = 0; ksp < 8; ksp++) {
#pragma unroll
            for (int nb = 0; nb < 16; nb++) {
                unsigned off = (unsigned)(((nb * 8 + ksp) * 32 + lane) << 2);
                uint4 B = *(const uint4*)(W1S + off);
                mma_tf32(acc[nb], A[2 * ksp][0], A[2 * ksp][1],
                         A[2 * ksp][2], A[2 * ksp][3], B.x, B.y);
                mma_tf32(acc[nb], A[2 * ksp + 1][0], A[2 * ksp + 1][1],
                         A[2 * ksp + 1][2], A[2 * ksp + 1][3], B.z, B.w);
            }
        }

        // ---- mid GN + relu -> Hf ----
        unsigned Hf[16][4];
        {
            float s1a = 0.f, s2a = 0.f, s1b = 0.f, s2b = 0.f;
#pragma unroll
            for (int nb = 0; nb < 16; nb++) {
                s1a += acc[nb][0] + acc[nb][1];
                s2a += acc[nb][0] * acc[nb][0] + acc[nb][1] * acc[nb][1];
                s1b += acc[nb][2] + acc[nb][3];
                s2b += acc[nb][2] * acc[nb][2] + acc[nb][3] * acc[nb][3];
            }
#pragma unroll
            for (int off = 1; off <= 2; off <<= 1) {
                s1a += __shfl_xor_sync(0xffffffffu, s1a, off);
                s2a += __shfl_xor_sync(0xffffffffu, s2a, off);
                s1b += __shfl_xor_sync(0xffffffffu, s1b, off);
                s2b += __shfl_xor_sync(0xffffffffu, s2b, off);
            }
            float mua = s1a * 0.0078125f;
            float rsa = rsqrtf(s2a * 0.0078125f - mua * mua + EPSn);
            float mub = s1b * 0.0078125f;
            float rsb = rsqrtf(s2b * 0.0078125f - mub * mub + EPSn);
#pragma unroll
            for (int nb = 0; nb < 16; nb++) {
                int c0 = 8 * nb + 2 * t;
                float ga = ps[256 + c0], gb = ps[257 + c0];
                float ba = ps[384 + c0], bb = ps[385 + c0];
                float h0 = fmaxf((acc[nb][0] - mua) * rsa * ga + ba, 0.f);
                float h1 = fmaxf((acc[nb][1] - mua) * rsa * gb + bb, 0.f);
                float h2 = fmaxf((acc[nb][2] - mub) * rsb * ga + ba, 0.f);
                float h3 = fmaxf((acc[nb][3] - mub) * rsb * gb + bb, 0.f);
                Hf[nb][0] = f2tf(h0); Hf[nb][1] = f2tf(h2);
                Hf[nb][2] = f2tf(h1); Hf[nb][3] = f2tf(h3);
            }
        }

        // ---- GEMM2: b @ Wm2 (ksp outer, nb inner) ----
#pragma unroll
        for (int nb = 0; nb < 16; nb++) {
            acc[nb][0] = 0.f; acc[nb][1] = 0.f; acc[nb][2] = 0.f; acc[nb][3] = 0.f;
        }
#pragma unroll
        for (int ksp = 0; ksp < 8; ksp++) {
#pragma unroll
            for (int nb = 0; nb < 16; nb++) {
                unsigned off = (unsigned)(((nb * 8 + ksp) * 32 + lane) << 2);
                uint4 B = *(const uint4*)(W2S + off);
                mma_tf32(acc[nb], Hf[2 * ksp][0], Hf[2 * ksp][1],
                         Hf[2 * ksp][2], Hf[2 * ksp][3], B.x, B.y);
                mma_tf32(acc[nb], Hf[2 * ksp + 1][0], Hf[2 * ksp + 1][1],
                         Hf[2 * ksp + 1][2], Hf[2 * ksp + 1][3], B.z, B.w);
            }
        }

        // ---- final GN + identity + relu -> out ----
        {
            float s1a = 0.f, s2a = 0.f, s1b = 0.f, s2b = 0.f;
#pragma unroll
            for (int nb = 0; nb < 16; nb++) {
                s1a += acc[nb][0] + acc[nb][1];
                s2a += acc[nb][0] * acc[nb][0] + acc[nb][1] * acc[nb][1];
                s1b += acc[nb][2] + acc[nb][3];
                s2b += acc[nb][2] * acc[nb][2] + acc[nb][3] * acc[nb][3];
            }
#pragma unroll
            for (int off = 1; off <= 2; off <<= 1) {
                s1a += __shfl_xor_sync(0xffffffffu, s1a, off);
                s2a += __shfl_xor_sync(0xffffffffu, s2a, off);
                s1b += __shfl_xor_sync(0xffffffffu, s1b, off);
                s2b += __shfl_xor_sync(0xffffffffu, s2b, off);
            }
            float mua = s1a * 0.0078125f;
            float rsa = rsqrtf(s2a * 0.0078125f - mua * mua + EPSn);
            float mub = s1b * 0.0078125f;
            float rsb = rsqrtf(s2b * 0.0078125f - mub * mub + EPSn);

            const float2* id0 = (const float2*)(tfeat + (size_t)r0c * 128);
            const float2* id8 = (const float2*)(tfeat + (size_t)r8c * 128);
            float2* o0 = (float2*)(out + (size_t)r0c * 128);
            float2* o8 = (float2*)(out + (size_t)r8c * 128);
#pragma unroll
            for (int nb = 0; nb < 16; nb++) {
                int c0 = 8 * nb + 2 * t;
                float ga = ps[512 + c0], gb = ps[513 + c0];
                float ba = ps[640 + c0], bb = ps[641 + c0];
                if (v0) {
                    float2 idv = id0[4 * nb + t];
                    float2 o;
                    o.x = fmaxf((acc[nb][0] - mua) * rsa * ga + ba + idv.x, 0.f);
                    o.y = fmaxf((acc[nb][1] - mua) * rsa * gb + bb + idv.y, 0.f);
                    o0[4 * nb + t] = o;
                }
                if (v8) {
                    float2 idv = id8[4 * nb + t];
                    float2 o;
                    o.x = fmaxf((acc[nb][2] - mub) * rsb * ga + ba + idv.x, 0.f);
                    o.y = fmaxf((acc[nb][3] - mub) * rsb * gb + bb + idv.y, 0.f);
                    o8[4 * nb + t] = o;
                }
            }
        }
    }
}

// ---------------------------------------------------------------------------
// launch
// ---------------------------------------------------------------------------
extern "C" void kernel_launch(void* const* d_in, const int* in_sizes, int n_in,
                              void* d_out, int out_size) {
    const float* context_feat = (const float*)d_in[0];
    const float* target_feat  = (const float*)d_in[1];
    const float* context_pose = (const float*)d_in[2];
    const float* target_pose  = (const float*)d_in[3];
    const int*   hi    = (const int*)d_in[4];
    const int*   wi    = (const int*)d_in[5];
    const float* W_in  = (const float*)d_in[6];
    const float* W_rp  = (const float*)d_in[7];
    const float* b_rp  = (const float*)d_in[8];
    const float* W_c1  = (const float*)d_in[9];
    const float* g_ctx = (const float*)d_in[10];
    const float* be_ctx= (const float*)d_in[11];
    const float* W_c2  = (const float*)d_in[12];
    const float* g_n   = (const float*)d_in[13];
    const float* be_n  = (const float*)d_in[14];
    const float* W_m1  = (const float*)d_in[15];
    const float* g_m1  = (const float*)d_in[16];
    const float* be_m1 = (const float*)d_in[17];
    const float* W_m2  = (const float*)d_in[18];
    const float* g_m2  = (const float*)d_in[19];
    const float* be_m2 = (const float*)d_in[20];

    int Nt = in_sizes[1] / 128;
    int E  = in_sizes[4];
    float* out = (float*)d_out;

    const int SMF = (32768 + 16384) * 4 + (128 * 4 + 384) * 4;  // 200192
    const int SM3 = (16384 + 16384) * 4 + 768 * 4;              // 134144

    cudaFuncSetAttribute(kfused,  cudaFuncAttributeMaxDynamicSharedMemorySize, SMF);
    cudaFuncSetAttribute(k3fused, cudaFuncAttributeMaxDynamicSharedMemorySize, SM3);

    k0_prep<<<128, 256>>>(W_in, W_c1, W_c2, W_m1, W_m2);
    kzero<<<296, 256>>>(Nt * 32);
    kfused<<<148, 256, SMF>>>(context_feat, context_pose, target_pose, hi, wi,
                              W_rp, b_rp, g_ctx, be_ctx, target_feat, E, Nt);
    k3fused<<<148, 256, SM3>>>(target_feat, g_n, be_n, g_m1, be_m1, g_m2, be_m2,
                               out, Nt);
}